// round 1
// baseline (speedup 1.0000x reference)
#include <cuda_runtime.h>
#include <cuda_bf16.h>
#include <cstddef>

// Problem constants
#define ROWS   128
#define T      30
#define W      5
#define OUT_T  26          // T - W + 1
#define NPAIRS 8256        // ROWS*(ROWS+1)/2
#define SPLIT  4           // pair-segments per batch
#define PPB    (NPAIRS / SPLIT)   // 2064 pairs per block
#define NTHREADS 256

// Padded stride for normalized rows: odd -> conflict-free when lanes read
// adjacent rows (bank = (r*31 + t) % 32, stride 31 coprime with 32).
#define XS_STRIDE 31

__device__ __forceinline__ int pair_offset(int i) {
    // number of pairs with first index < i : sum_{k<i} (ROWS - k)
    return i * ROWS - (i * (i - 1)) / 2;
}

__global__ __launch_bounds__(NTHREADS)
void ts_cov_kernel(const float* __restrict__ in, float* __restrict__ out) {
    const int batch = blockIdx.x;
    const int seg   = blockIdx.y;

    __shared__ float raw[ROWS * T];            // 15360 B
    __shared__ float xs[ROWS * XS_STRIDE];     // 15872 B

    // ---- Stage input (coalesced) ----
    const float* gin = in + (size_t)batch * (ROWS * T);
    for (int idx = threadIdx.x; idx < ROWS * T; idx += NTHREADS)
        raw[idx] = gin[idx];
    __syncthreads();

    // ---- Per-row normalization (population std), one thread per row ----
    if (threadIdx.x < ROWS) {
        const int r = threadIdx.x;
        float s = 0.f;
#pragma unroll
        for (int t = 0; t < T; t++) s += raw[r * T + t];
        const float mean = s * (1.0f / T);
        float v = 0.f;
#pragma unroll
        for (int t = 0; t < T; t++) {
            float c = raw[r * T + t] - mean;
            v += c * c;
        }
        const float inv = rsqrtf(v * (1.0f / T));
#pragma unroll
        for (int t = 0; t < T; t++)
            xs[r * XS_STRIDE + t] = (raw[r * T + t] - mean) * inv;
    }
    __syncthreads();

    // ---- Pairwise sliding-window means ----
    float* gout = out + (size_t)batch * ((size_t)NPAIRS * OUT_T);

    const int p_end = (seg + 1) * PPB;
    for (int p = seg * PPB + threadIdx.x; p < p_end; p += NTHREADS) {
        // Map flat pair index p -> (i, j), i <= j.
        // Solve i^2 - (2*ROWS+1) i + 2p = 0  ->  i = (257 - sqrt(257^2 - 8p)) / 2
        int i = (int)((257.0f - sqrtf(66049.0f - 8.0f * (float)p)) * 0.5f);
        if (i < 0) i = 0;
        if (i > ROWS - 1) i = ROWS - 1;
        while (i + 1 <= ROWS - 1 && pair_offset(i + 1) <= p) ++i;
        while (i > 0 && pair_offset(i) > p) --i;
        const int j = p - pair_offset(i) + i;

        const float* xi = xs + i * XS_STRIDE;
        const float* xj = xs + j * XS_STRIDE;

        float a[T], b[T];
#pragma unroll
        for (int t = 0; t < T; t++) { a[t] = xi[t]; b[t] = xj[t]; }

        float2* go = (float2*)(gout + (size_t)p * OUT_T);  // p*104 B, 8-aligned

        float s = a[0] * b[0];
        s += a[1] * b[1];
        s += a[2] * b[2];
        s += a[3] * b[3];
        s += a[4] * b[4];
        float prev = s * 0.2f;
#pragma unroll
        for (int k = 1; k < OUT_T; k++) {
            s += a[k + 4] * b[k + 4] - a[k - 1] * b[k - 1];
            float cur = s * 0.2f;
            if (k & 1) {
                go[k >> 1] = make_float2(prev, cur);
            } else {
                prev = cur;
            }
        }
        // OUT_T is even (26): k=1,3,...,25 emit 13 float2 stores covering all 26.
    }
}

extern "C" void kernel_launch(void* const* d_in, const int* in_sizes, int n_in,
                              void* d_out, int out_size) {
    const float* in = (const float*)d_in[0];
    float* out = (float*)d_out;
    const int B = in_sizes[0] / (ROWS * T);
    dim3 grid(B, SPLIT);
    ts_cov_kernel<<<grid, NTHREADS>>>(in, out);
}

// round 2
// speedup vs baseline: 2.5721x; 2.5721x over previous
#include <cuda_runtime.h>
#include <cuda_bf16.h>
#include <cstddef>

// Problem constants
#define ROWS   128
#define T      30
#define W      5
#define OUT_T  26          // T - W + 1
#define NPAIRS 8256        // ROWS*(ROWS+1)/2
#define NTHREADS 256
#define NWARPS   8
#define GSEG     8                     // CTAs per batch
#define CHUNKS   (NPAIRS / 32)         // 258 chunks of 32 pairs

// Padded stride for normalized rows: odd -> conflict-free when lanes read
// adjacent rows (bank = (r*31 + t) % 32, stride 31 coprime with 32).
#define XS_STRIDE 31

__device__ __forceinline__ int pair_offset(int i) {
    // number of pairs with first index < i : sum_{k<i} (ROWS - k)
    return i * ROWS - (i * (i - 1)) / 2;
}

__global__ __launch_bounds__(NTHREADS)
void ts_cov_kernel(const float* __restrict__ in, float* __restrict__ out) {
    const int batch = blockIdx.x;
    const int seg   = blockIdx.y;

    // stage doubles as: (a) raw-input staging during normalization (needs
    // 128*30 = 3840 floats), (b) per-warp result staging afterwards
    // (8 warps * 832 floats = 6656 floats). 26624 B.
    __shared__ float stage[NWARPS * 32 * OUT_T];
    __shared__ float xs[ROWS * XS_STRIDE];          // 15872 B

    // ---- Stage input (coalesced) ----
    const float* gin = in + (size_t)batch * (ROWS * T);
    for (int idx = threadIdx.x; idx < ROWS * T; idx += NTHREADS)
        stage[idx] = gin[idx];
    __syncthreads();

    // ---- Per-row normalization (population std), one thread per row ----
    if (threadIdx.x < ROWS) {
        const int r = threadIdx.x;
        float s = 0.f;
#pragma unroll
        for (int t = 0; t < T; t++) s += stage[r * T + t];
        const float mean = s * (1.0f / T);
        float v = 0.f;
#pragma unroll
        for (int t = 0; t < T; t++) {
            float c = stage[r * T + t] - mean;
            v += c * c;
        }
        const float inv = rsqrtf(v * (1.0f / T));
#pragma unroll
        for (int t = 0; t < T; t++)
            xs[r * XS_STRIDE + t] = (stage[r * T + t] - mean) * inv;
    }
    __syncthreads();   // xs ready; stage[] free for reuse as result staging

    // ---- Pairwise sliding-window means, warp-chunked ----
    const int wid  = threadIdx.x >> 5;
    const int lane = threadIdx.x & 31;
    const int gw   = seg * NWARPS + wid;            // global warp id in batch
    float* sw = stage + wid * (32 * OUT_T);         // warp-private staging
    float* gout = out + (size_t)batch * ((size_t)NPAIRS * OUT_T);

    for (int c = gw; c < CHUNKS; c += GSEG * NWARPS) {
        const int p = c * 32 + lane;

        // Map flat pair index p -> (i, j), i <= j.
        // i ~ (257 - sqrt(257^2 - 8p)) / 2, then bounded correction.
        int i = (int)((257.0f - sqrtf(66049.0f - 8.0f * (float)p)) * 0.5f);
        if (i < 0) i = 0;
        if (i > ROWS - 1) i = ROWS - 1;
        while (i + 1 <= ROWS - 1 && pair_offset(i + 1) <= p) ++i;
        while (i > 0 && pair_offset(i) > p) --i;
        const int j = p - pair_offset(i) + i;

        const float* xi = xs + i * XS_STRIDE;
        const float* xj = xs + j * XS_STRIDE;

        float a[T], b[T];
#pragma unroll
        for (int t = 0; t < T; t++) { a[t] = xi[t]; b[t] = xj[t]; }

        // Sliding window; stage results in smem [pair][k], stride OUT_T.
        float* srow = sw + lane * OUT_T;
        float s = a[0] * b[0];
        s += a[1] * b[1];
        s += a[2] * b[2];
        s += a[3] * b[3];
        s += a[4] * b[4];
        srow[0] = s * 0.2f;
#pragma unroll
        for (int k = 1; k < OUT_T; k++) {
            s += a[k + 4] * b[k + 4] - a[k - 1] * b[k - 1];
            srow[k] = s * 0.2f;
        }
        __syncwarp();

        // Coalesced copy-out: 832 contiguous floats = 416 float2.
        // Region base = c*832 floats (16B aligned: 832*4*c).
        const float2* s2 = (const float2*)sw;
        float2* g2 = (float2*)(gout + (size_t)c * (32 * OUT_T));
#pragma unroll
        for (int m = 0; m < 13; m++)
            g2[m * 32 + lane] = s2[m * 32 + lane];
        __syncwarp();   // protect sw before next iteration's STS
    }
}

extern "C" void kernel_launch(void* const* d_in, const int* in_sizes, int n_in,
                              void* d_out, int out_size) {
    const float* in = (const float*)d_in[0];
    float* out = (float*)d_out;
    const int B = in_sizes[0] / (ROWS * T);
    dim3 grid(B, GSEG);
    ts_cov_kernel<<<grid, NTHREADS>>>(in, out);
}

// round 3
// speedup vs baseline: 2.6967x; 1.0484x over previous
#include <cuda_runtime.h>
#include <cuda_bf16.h>
#include <cstddef>

// Problem constants
#define ROWS   128
#define T      30
#define W      5
#define OUT_T  26          // T - W + 1
#define NPAIRS 8256        // ROWS*(ROWS+1)/2
#define NTHREADS 256
#define NWARPS   8

// xs: normalized rows, stride 33 (odd -> conflict-free for lane-consecutive
// row reads AND distinct-bank k-major staging interplay).
#define XS_STRIDE 33
// per-warp k-major staging: 26 rows of 33 floats
#define STG_ROWS  26
#define STG_STRIDE 33
#define STG_WORDS (STG_ROWS * STG_STRIDE)   // 858

// 10 (jb, is) tiles per batch (is <= jb), 32 i-iterations each => 320 units.
// Each of 8 warps owns a contiguous range of 40 units.

__device__ __forceinline__ int pair_offset(int i) {
    return i * ROWS - (i * (i - 1)) / 2;   // pairs with first index < i
}

__global__ __launch_bounds__(NTHREADS, 2)
void ts_cov_kernel(const float* __restrict__ in, float* __restrict__ out) {
    const int batch = blockIdx.x;

    __shared__ float xs[ROWS * XS_STRIDE];            // 16896 B
    __shared__ float stage[NWARPS * STG_WORDS];       // 27456 B (doubles as raw staging)

    // ---- Stage raw input (coalesced) into stage[] ----
    const float* gin = in + (size_t)batch * (ROWS * T);
    for (int idx = threadIdx.x; idx < ROWS * T; idx += NTHREADS)
        stage[idx] = gin[idx];
    __syncthreads();

    // ---- Per-row normalization (population std), one thread per row ----
    if (threadIdx.x < ROWS) {
        const int r = threadIdx.x;
        float s = 0.f;
#pragma unroll
        for (int t = 0; t < T; t++) s += stage[r * T + t];
        const float mean = s * (1.0f / T);
        float v = 0.f;
#pragma unroll
        for (int t = 0; t < T; t++) {
            float c = stage[r * T + t] - mean;
            v += c * c;
        }
        const float inv = rsqrtf(v * (1.0f / T));
#pragma unroll
        for (int t = 0; t < T; t++)
            xs[r * XS_STRIDE + t] = (stage[r * T + t] - mean) * inv;
    }
    __syncthreads();   // xs ready; stage[] now reused as per-warp result staging

    const int wid  = threadIdx.x >> 5;
    const int lane = threadIdx.x & 31;
    float* sw = stage + wid * STG_WORDS;
    float* gout = out + (size_t)batch * ((size_t)NPAIRS * OUT_T);

    const int uA = wid * 40;
    const int uB = uA + 40;

    for (int tile = (uA >> 5); tile <= ((uB - 1) >> 5); ++tile) {
        // tile -> (jb, is): triangular enumeration (0,0)(1,0)(1,1)(2,0)...(3,3)
        const int jb = (tile >= 6) ? 3 : (tile >= 3) ? 2 : (tile >= 1) ? 1 : 0;
        const int is = tile - (jb * (jb + 1)) / 2;
        const int j0 = jb * 32;

        // b rows register-resident for this tile: row j0+lane
        float b[T];
#pragma unroll
        for (int t = 0; t < T; t++)
            b[t] = xs[(j0 + lane) * XS_STRIDE + t];

        const int loU = max(uA, tile * 32);
        const int hiU = min(uB, tile * 32 + 32);

        for (int u = loU; u < hiU; ++u) {
            const int i = is * 32 + (u - tile * 32);

            // cooperative fetch of row i, then shuffle-broadcast products
            float va = 0.f;
            if (lane < T) va = xs[i * XS_STRIDE + lane];

            float p[T];
#pragma unroll
            for (int t = 0; t < T; t++)
                p[t] = __shfl_sync(0xffffffffu, va, t) * b[t];

            // sliding window of 5, staged k-major: stage[k][lane]
            float s = p[0] + p[1] + p[2] + p[3] + p[4];
            sw[lane] = s * 0.2f;
#pragma unroll
            for (int k = 1; k < OUT_T; k++) {
                s += p[k + 4] - p[k - 1];
                sw[k * STG_STRIDE + lane] = s * 0.2f;
            }
            __syncwarp();

            // Coalesced copy-out of the valid pairs (j >= i within this j-block)
            int lo = i - j0;
            if (lo < 0) lo = 0;
            const int count = 32 - lo;              // active pairs
            const int total = count * OUT_T;
            const size_t p_start = (size_t)pair_offset(i) + (size_t)(j0 + lo - i);
            float* basep = gout + p_start * OUT_T;

            // w = q*26 + k  ->  staged at [k][lo+q]; increment-tracked q,k
            int q  = (lane >= OUT_T) ? 1 : 0;
            int k2 = lane - OUT_T * q;
            for (int w = lane; w < total; w += 32) {
                basep[w] = sw[k2 * STG_STRIDE + lo + q];
                k2 += 32 - OUT_T;   // +6
                q  += 1;
                if (k2 >= OUT_T) { k2 -= OUT_T; q += 1; }
            }
            __syncwarp();
        }
    }
}

extern "C" void kernel_launch(void* const* d_in, const int* in_sizes, int n_in,
                              void* d_out, int out_size) {
    const float* in = (const float*)d_in[0];
    float* out = (float*)d_out;
    const int B = in_sizes[0] / (ROWS * T);
    ts_cov_kernel<<<B, NTHREADS>>>(in, out);
}

// round 4
// speedup vs baseline: 2.7281x; 1.0116x over previous
#include <cuda_runtime.h>
#include <cuda_bf16.h>
#include <cstddef>

#define ROWS   128
#define T      30
#define OUT_T  26
#define NPAIRS 8256
#define NTHREADS 256
#define NWARPS   8
#define GSEG     2          // CTAs per batch
#define UNITS    320        // 10 tiles * 32 i-iterations
#define UPW      (UNITS / (GSEG * NWARPS))   // 20 units per warp

#define XS_STRIDE 36        // 144 B rows: 16B-aligned for float4 broadcast loads
#define STG_STRIDE 33       // k-major staging stride (odd -> conflict-free)
#define STG_WORDS (OUT_T * STG_STRIDE)   // 858

__device__ __forceinline__ int pair_offset(int i) {
    return i * ROWS - (i * (i - 1)) / 2;
}

__device__ __forceinline__ int div26(int w) {   // exact floor(w/26) for 0<=w<832
    return (w * 10083) >> 18;
}

__global__ __launch_bounds__(NTHREADS, 2)
void ts_cov_kernel(const float* __restrict__ in, float* __restrict__ out) {
    const int batch = blockIdx.x;
    const int seg   = blockIdx.y;

    __shared__ float xs[ROWS * XS_STRIDE];          // 18432 B
    __shared__ float stage[NWARPS * STG_WORDS];     // 27456 B (doubles as raw staging)

    // ---- Stage raw input (coalesced) ----
    const float* gin = in + (size_t)batch * (ROWS * T);
    for (int idx = threadIdx.x; idx < ROWS * T; idx += NTHREADS)
        stage[idx] = gin[idx];
    __syncthreads();

    // ---- Per-row normalization (population std) ----
    if (threadIdx.x < ROWS) {
        const int r = threadIdx.x;
        float s = 0.f;
#pragma unroll
        for (int t = 0; t < T; t++) s += stage[r * T + t];
        const float mean = s * (1.0f / T);
        float v = 0.f;
#pragma unroll
        for (int t = 0; t < T; t++) {
            float c = stage[r * T + t] - mean;
            v += c * c;
        }
        const float inv = rsqrtf(v * (1.0f / T));
#pragma unroll
        for (int t = 0; t < T; t++)
            xs[r * XS_STRIDE + t] = (stage[r * T + t] - mean) * inv;
    }
    __syncthreads();   // xs ready; stage[] reused as per-warp staging

    const int wid  = threadIdx.x >> 5;
    const int lane = threadIdx.x & 31;
    const int gw   = seg * NWARPS + wid;        // global warp id within batch
    float* sw = stage + wid * STG_WORDS;
    float* gout = out + (size_t)batch * ((size_t)NPAIRS * OUT_T);

    const int uA = gw * UPW;
    const int uB = uA + UPW;

    for (int tile = (uA >> 5); tile <= ((uB - 1) >> 5); ++tile) {
        // tile -> (jb, is), triangular enumeration with is <= jb
        const int jb = (tile >= 6) ? 3 : (tile >= 3) ? 2 : (tile >= 1) ? 1 : 0;
        const int is = tile - (jb * (jb + 1)) / 2;
        const int j0 = jb * 32;

        // b row (j0+lane) register-resident for this tile (float4 loads)
        float b[T];
        {
            const float4* bp = (const float4*)(xs + (j0 + lane) * XS_STRIDE);
#pragma unroll
            for (int m = 0; m < 7; m++) {
                float4 v4 = bp[m];
                b[m * 4 + 0] = v4.x; b[m * 4 + 1] = v4.y;
                b[m * 4 + 2] = v4.z; b[m * 4 + 3] = v4.w;
            }
            float2 v2 = *(const float2*)(xs + (j0 + lane) * XS_STRIDE + 28);
            b[28] = v2.x; b[29] = v2.y;
        }

        const int loU = max(uA, tile * 32);
        const int hiU = min(uB, tile * 32 + 32);

        for (int u = loU; u < hiU; ++u) {
            const int i = is * 32 + (u - tile * 32);

            // Broadcast-load row i (8 wavefronts), form products
            float p[T];
            {
                const float4* ap = (const float4*)(xs + i * XS_STRIDE);
#pragma unroll
                for (int m = 0; m < 7; m++) {
                    float4 v4 = ap[m];
                    p[m * 4 + 0] = v4.x * b[m * 4 + 0];
                    p[m * 4 + 1] = v4.y * b[m * 4 + 1];
                    p[m * 4 + 2] = v4.z * b[m * 4 + 2];
                    p[m * 4 + 3] = v4.w * b[m * 4 + 3];
                }
                float2 v2 = *(const float2*)(xs + i * XS_STRIDE + 28);
                p[28] = v2.x * b[28];
                p[29] = v2.y * b[29];
            }

            // Sliding window of 5, staged k-major: sw[k*33 + lane]
            float s = p[0] + p[1] + p[2] + p[3] + p[4];
            sw[lane] = s * 0.2f;
#pragma unroll
            for (int k = 1; k < OUT_T; k++) {
                s += p[k + 4] - p[k - 1];
                sw[k * STG_STRIDE + lane] = s * 0.2f;
            }
            __syncwarp();

            // Coalesced copy-out
            const int lo = (i > j0) ? (i - j0) : 0;
            const size_t p_start = (size_t)pair_offset(i) + (size_t)(j0 + lo - i);
            float* basep = gout + p_start * OUT_T;

            if (lo == 0) {
                // full tile: 832 floats, branch-free unrolled
#pragma unroll
                for (int m = 0; m < OUT_T; m++) {
                    const int w = m * 32 + lane;
                    const int q = div26(w);
                    const int k = w - q * OUT_T;
                    basep[w] = sw[k * STG_STRIDE + q];
                }
            } else {
                const int total = (32 - lo) * OUT_T;
#pragma unroll
                for (int m = 0; m < OUT_T; m++) {
                    const int w = m * 32 + lane;
                    if (w < total) {
                        const int q = div26(w);
                        const int k = w - q * OUT_T;
                        basep[w] = sw[k * STG_STRIDE + lo + q];
                    }
                }
            }
            __syncwarp();   // protect sw before next iteration's STS
        }
    }
}

extern "C" void kernel_launch(void* const* d_in, const int* in_sizes, int n_in,
                              void* d_out, int out_size) {
    const float* in = (const float*)d_in[0];
    float* out = (float*)d_out;
    const int B = in_sizes[0] / (ROWS * T);
    dim3 grid(B, GSEG);
    ts_cov_kernel<<<grid, NTHREADS>>>(in, out);
}